// round 15
// baseline (speedup 1.0000x reference)
#include <cuda_runtime.h>
#include <cuda_bf16.h>
#include <cooperative_groups.h>
#include <cstdint>
#include <cstddef>

namespace cg = cooperative_groups;
using u64 = unsigned long long;

#define BATCH 128
#define TLEN  1024
#define HID   256
#define G4    1024  // 4*HID
#define HPAD  260   // hbuf row stride (pad 4 -> conflict-free b-frag LDS)

// ---------------- misc helpers ----------------
__device__ __forceinline__ float sigm_f(float x) {
    x = fminf(fmaxf(x, -30.f), 30.f);
    return __fdividef(1.f, 1.f + __expf(-x));
}
__device__ __forceinline__ float tanh_f(float x) {
    x = fminf(fmaxf(x, -15.f), 15.f);
    float e = __expf(2.f * x);
    return __fdividef(e - 1.f, e + 1.f);
}

// ---------------- tf32 mma helpers ----------------
__device__ __forceinline__ unsigned cvt_tf32(float f) {
    unsigned r;
    asm("cvt.rna.tf32.f32 %0, %1;" : "=r"(r) : "f"(f));
    return r;
}
__device__ __forceinline__ void mma_tf32(float* d, const unsigned* a, const unsigned* b) {
    asm("mma.sync.aligned.m16n8k8.row.col.f32.tf32.tf32.f32 "
        "{%0,%1,%2,%3},{%4,%5,%6,%7},{%8,%9},{%0,%1,%2,%3};"
        : "+f"(d[0]), "+f"(d[1]), "+f"(d[2]), "+f"(d[3])
        : "r"(a[0]), "r"(a[1]), "r"(a[2]), "r"(a[3]), "r"(b[0]), "r"(b[1]));
}

// ---------------- cluster async-store primitives ----------------
__device__ __forceinline__ unsigned smem_u32(const void* p) {
    return (unsigned)__cvta_generic_to_shared(p);
}
__device__ __forceinline__ unsigned mapa_u32(unsigned laddr, unsigned rank) {
    unsigned r;
    asm("mapa.shared::cluster.u32 %0, %1, %2;" : "=r"(r) : "r"(laddr), "r"(rank));
    return r;
}
__device__ __forceinline__ void st_async_u32(unsigned raddr, unsigned v, unsigned rmbar) {
    asm volatile("st.async.shared::cluster.mbarrier::complete_tx::bytes.b32 [%0], %1, [%2];"
                 :: "r"(raddr), "r"(v), "r"(rmbar) : "memory");
}
__device__ __forceinline__ void mbar_init(unsigned mbar, unsigned cnt) {
    asm volatile("mbarrier.init.shared.b64 [%0], %1;" :: "r"(mbar), "r"(cnt) : "memory");
}
__device__ __forceinline__ void mbar_expect_tx(unsigned mbar, unsigned bytes) {
    asm volatile("mbarrier.arrive.expect_tx.shared.b64 _, [%0], %1;"
                 :: "r"(mbar), "r"(bytes) : "memory");
}
__device__ __forceinline__ void mbar_wait_cluster(unsigned mbar, unsigned parity) {
    asm volatile(
        "{\n\t"
        ".reg .pred P;\n"
        "LWAIT_%=:\n\t"
        "mbarrier.try_wait.parity.acquire.cluster.shared::cta.b64 P, [%0], %1, 0x989680;\n\t"
        "@P bra LDONE_%=;\n\t"
        "bra LWAIT_%=;\n"
        "LDONE_%=:\n\t"
        "}"
        :: "r"(mbar), "r"(parity) : "memory");
}

// ---------------- scratch (static device globals) ----------------
__device__ float g_xw[(size_t)BATCH * TLEN * G4];     // 512 MB, reused by both layers
__device__ float g_hseq[(size_t)BATCH * TLEN * HID];  // 128 MB
__device__ float g_hlast[BATCH * HID];

// ---------------------------------------------------------------------------
// tf32 GEMM (R12 version): C[M,1024] = A[M,K] @ B[K,1024] + bias
// 128x128 CTA tile, BK=32, 8 warps (2m x 4n), warp tile 64x32, m16n8k8.
// ---------------------------------------------------------------------------
__global__ __launch_bounds__(256, 2)
void gemm_tf32_bias(const float* __restrict__ A, const float* __restrict__ B,
                    const float* __restrict__ bias, float* __restrict__ C, int K)
{
    __shared__ unsigned As[128][36];
    __shared__ unsigned Bs[32][136];

    const int tid = threadIdx.x;
    const int n0  = blockIdx.x * 128;
    const size_t m0 = (size_t)blockIdx.y * 128;
    const int warp = tid >> 5, lane = tid & 31;
    const int wm = (warp >> 2) * 64;
    const int wn = (warp & 3) * 32;
    const int g  = lane >> 2;
    const int tg = lane & 3;

    float acc[4][4][4];
#pragma unroll
    for (int mf = 0; mf < 4; mf++)
#pragma unroll
        for (int nf = 0; nf < 4; nf++)
#pragma unroll
            for (int i = 0; i < 4; i++) acc[mf][nf][i] = 0.f;

    for (int kb = 0; kb < K; kb += 32) {
#pragma unroll
        for (int i = 0; i < 4; i++) {
            int idx = tid + i * 256;
            int r = idx >> 3, c4 = (idx & 7) * 4;
            float4 v = *(const float4*)&A[(m0 + r) * K + kb + c4];
            uint4 t;
            t.x = cvt_tf32(v.x); t.y = cvt_tf32(v.y);
            t.z = cvt_tf32(v.z); t.w = cvt_tf32(v.w);
            *(uint4*)&As[r][c4] = t;
        }
#pragma unroll
        for (int i = 0; i < 4; i++) {
            int idx = tid + i * 256;
            int r = idx >> 5, c4 = (idx & 31) * 4;
            float4 v = *(const float4*)&B[(size_t)(kb + r) * G4 + n0 + c4];
            uint4 t;
            t.x = cvt_tf32(v.x); t.y = cvt_tf32(v.y);
            t.z = cvt_tf32(v.z); t.w = cvt_tf32(v.w);
            *(uint4*)&Bs[r][c4] = t;
        }
        __syncthreads();

#pragma unroll
        for (int ks = 0; ks < 4; ks++) {
            const int k0 = ks * 8;
            unsigned af[4][4], bf[4][2];
#pragma unroll
            for (int mf = 0; mf < 4; mf++) {
                int row = wm + mf * 16;
                af[mf][0] = As[row + g][k0 + tg];
                af[mf][1] = As[row + g + 8][k0 + tg];
                af[mf][2] = As[row + g][k0 + tg + 4];
                af[mf][3] = As[row + g + 8][k0 + tg + 4];
            }
#pragma unroll
            for (int nf = 0; nf < 4; nf++) {
                int col = wn + nf * 8;
                bf[nf][0] = Bs[k0 + tg][col + g];
                bf[nf][1] = Bs[k0 + tg + 4][col + g];
            }
#pragma unroll
            for (int mf = 0; mf < 4; mf++)
#pragma unroll
                for (int nf = 0; nf < 4; nf++)
                    mma_tf32(acc[mf][nf], af[mf], bf[nf]);
        }
        __syncthreads();
    }

#pragma unroll
    for (int nf = 0; nf < 4; nf++) {
        int col = n0 + wn + nf * 8 + 2 * tg;
        float b0 = bias[col], b1 = bias[col + 1];
#pragma unroll
        for (int mf = 0; mf < 4; mf++) {
            size_t row = m0 + wm + mf * 16 + g;
            float2 v0 = {acc[mf][nf][0] + b0, acc[mf][nf][1] + b1};
            float2 v1 = {acc[mf][nf][2] + b0, acc[mf][nf][3] + b1};
            *(float2*)&C[row * G4 + col] = v0;
            *(float2*)&C[(row + 8) * G4 + col] = v1;
        }
    }
}

// ---------------------------------------------------------------------------
// Persistent-cluster LSTM recurrence — tensor-core phase 1, FOUR independent
// mma accumulation chains (8-deep each) to halve exposed HMMA dependent
// latency on the critical inter-step chain.
// Grid: 128 CTAs = 16 clusters x 8 CTAs, 256 threads = 8 warps.
// Warp w owns 16 gate-cols; per group: D[16x8] = U^T[16x256] h^T[256x8]
// via 32 x mma.m16n8k8 (rows 4..7 zero-padded). U^T frags in registers.
// Exchange / two-group pipeline / barriers identical to R14 champion.
// ---------------------------------------------------------------------------
template <bool WRITE_SEQ>
__global__ void __cluster_dims__(8, 1, 1) __launch_bounds__(256, 1)
lstm_layer(const float* __restrict__ xw, const float* __restrict__ U,
           float* __restrict__ out_seq, float* __restrict__ out_last)
{
    __shared__ __align__(16) unsigned hbuf[2][8][HPAD]; // tf32 bits, dbl-buffered
    __shared__ float part[2][4][128];                   // [grp][row][gc]
    __shared__ __align__(8) u64 mbars[4];               // [buf*2+grp]

    cg::cluster_group cluster = cg::this_cluster();
    const int tid  = threadIdx.x;
    const int rank = (int)cluster.block_rank();
    const int cid  = blockIdx.x >> 3;
    const int b0   = cid * 8;

    const int warp = tid >> 5, lane = tid & 31;
    const int g  = lane >> 2;          // 0..7
    const int tg = lane & 3;           // 0..3
    const bool brow = (g < 4);         // lane supplies a real B row

    // epilogue roles: warp er owns batch row er
    const int er   = warp;             // 0..7
    const int ec   = lane;             // 0..31
    const int egrp = er >> 2;
    const int erow = er & 3;

    // global column for this warp's m-index
    const int colbase = (warp >> 1) * 256 + rank * 32 + (warp & 1) * 16;

    // U^T fragments: 32 k-chunks x 4 regs (tf32)
    unsigned ua[32][4];
#pragma unroll
    for (int kc = 0; kc < 32; kc++) {
        const int k0 = kc * 8;
        ua[kc][0] = cvt_tf32(U[(size_t)(k0 + tg) * G4 + colbase + g]);
        ua[kc][1] = cvt_tf32(U[(size_t)(k0 + tg) * G4 + colbase + 8 + g]);
        ua[kc][2] = cvt_tf32(U[(size_t)(k0 + tg + 4) * G4 + colbase + g]);
        ua[kc][3] = cvt_tf32(U[(size_t)(k0 + tg + 4) * G4 + colbase + 8 + g]);
    }

    // init smem
    for (int i = tid; i < 2 * 8 * HPAD; i += 256) ((unsigned*)hbuf)[i] = 0u;
    const unsigned mbar0 = smem_u32(&mbars[0]);
    if (tid == 0) {
#pragma unroll
        for (int i = 0; i < 4; i++) mbar_init(mbar0 + 8u * i, 1);
    }

    // per-rank remote addresses
    const unsigned hloc = smem_u32(&hbuf[0][er][rank * 32 + ec]);
    unsigned rH[8], rM[8];
#pragma unroll
    for (int pr = 0; pr < 8; pr++) {
        rH[pr] = mapa_u32(hloc, pr);
        rM[pr] = mapa_u32(mbar0, pr);
    }

    cluster.sync();   // barriers + zeroed hbuf visible cluster-wide
    if (tid == 0) {
#pragma unroll
        for (int i = 0; i < 4; i++) mbar_expect_tx(mbar0 + 8u * i, 4096);
    }

    const float* xptr = xw + ((size_t)(b0 + er) * TLEN) * G4 + rank * 32 + ec;
    float* hptr = WRITE_SEQ
        ? out_seq + ((size_t)(b0 + er) * TLEN) * HID + rank * 32 + ec
        : nullptr;

    float c_state = 0.f;
    unsigned pp00 = 0, pp01 = 0, pp10 = 0, pp11 = 0;  // parity[buf][grp]

    for (int t = 0; t < TLEN; t++) {
        const int p  = t & 1;
        const int nb = p ^ 1;
        const unsigned hoff = (unsigned)(nb * 8 * HPAD) * 4u;
        const unsigned moffG = (unsigned)(nb * 2 + egrp) * 8u;

        // prefetch own row's xw gate inputs
        float xg0 = xptr[0];
        float xg1 = xptr[HID];
        float xg2 = xptr[2 * HID];
        float xg3 = xptr[3 * HID];
        xptr += G4;

#pragma unroll
        for (int grp = 0; grp < 2; grp++) {
            // ---- wait for this buffer+group's h from all ranks ----
            if (t > 0) {
                const unsigned mb = mbar0 + (unsigned)(p * 2 + grp) * 8u;
                if (p == 0) {
                    if (grp == 0) { mbar_wait_cluster(mb, pp00); pp00 ^= 1; }
                    else          { mbar_wait_cluster(mb, pp01); pp01 ^= 1; }
                } else {
                    if (grp == 0) { mbar_wait_cluster(mb, pp10); pp10 ^= 1; }
                    else          { mbar_wait_cluster(mb, pp11); pp11 ^= 1; }
                }
                if (tid == 0) mbar_expect_tx(mb, 4096);   // re-arm
            }

            // ---- phase 1: D[16x8] = U^T @ h^T via 32 mma, 4 indep chains ----
            float d0[4] = {0.f, 0.f, 0.f, 0.f};
            float d1[4] = {0.f, 0.f, 0.f, 0.f};
            float d2[4] = {0.f, 0.f, 0.f, 0.f};
            float d3[4] = {0.f, 0.f, 0.f, 0.f};
            const unsigned* hrow = &hbuf[p][grp * 4 + (brow ? g : 0)][0];
#pragma unroll
            for (int kc = 0; kc < 32; kc += 4) {
                unsigned b0f[2], b1f[2], b2f[2], b3f[2];
                if (brow) {
                    b0f[0] = hrow[kc * 8 + tg];
                    b0f[1] = hrow[kc * 8 + tg + 4];
                    b1f[0] = hrow[kc * 8 + 8 + tg];
                    b1f[1] = hrow[kc * 8 + 8 + tg + 4];
                    b2f[0] = hrow[kc * 8 + 16 + tg];
                    b2f[1] = hrow[kc * 8 + 16 + tg + 4];
                    b3f[0] = hrow[kc * 8 + 24 + tg];
                    b3f[1] = hrow[kc * 8 + 24 + tg + 4];
                } else {
                    b0f[0] = b0f[1] = b1f[0] = b1f[1] = 0u;
                    b2f[0] = b2f[1] = b3f[0] = b3f[1] = 0u;
                }
                mma_tf32(d0, ua[kc], b0f);
                mma_tf32(d1, ua[kc + 1], b1f);
                mma_tf32(d2, ua[kc + 2], b2f);
                mma_tf32(d3, ua[kc + 3], b3f);
            }
            if (tg < 2) {   // real batch rows live in n = 2tg, 2tg+1 (< 4)
                part[grp][2 * tg][warp * 16 + g]         = (d0[0] + d1[0]) + (d2[0] + d3[0]);
                part[grp][2 * tg + 1][warp * 16 + g]     = (d0[1] + d1[1]) + (d2[1] + d3[1]);
                part[grp][2 * tg][warp * 16 + 8 + g]     = (d0[2] + d1[2]) + (d2[2] + d3[2]);
                part[grp][2 * tg + 1][warp * 16 + 8 + g] = (d0[3] + d1[3]) + (d2[3] + d3[3]);
            }
            __syncthreads();

            // ---- epilogue for this group (warps whose rows belong to it) ----
            if (egrp == grp) {
                float v0 = xg0 + part[grp][erow][ec];
                float v1 = xg1 + part[grp][erow][32 + ec];
                float v2 = xg2 + part[grp][erow][64 + ec];
                float v3 = xg3 + part[grp][erow][96 + ec];
                float ig = sigm_f(v0);
                float fg = sigm_f(v1);
                float gg = tanh_f(v2);
                float og = sigm_f(v3);
                c_state = fg * c_state + ig * gg;
                float hnew = og * tanh_f(c_state);

                if (WRITE_SEQ) { *hptr = hnew; hptr += HID; }

                if (t < TLEN - 1) {
                    const unsigned hb = cvt_tf32(hnew);
#pragma unroll
                    for (int pr = 0; pr < 8; pr++)
                        st_async_u32(rH[pr] + hoff, hb, rM[pr] + moffG);
                } else if (!WRITE_SEQ) {
                    out_last[(size_t)(b0 + er) * HID + rank * 32 + ec] = hnew;
                }
            }
        }
    }

    cluster.sync();   // don't exit with peer-targeted async traffic in flight
}

// ---------------------------------------------------------------------------
// Dense head: out[b] = relu( relu(h_last[b] @ Wd1 + bd1) @ Wd2 + bd2 )
// ---------------------------------------------------------------------------
__global__ __launch_bounds__(128)
void dense_head_kernel(const float* __restrict__ hlast,
                       const float* __restrict__ Wd1, const float* __restrict__ bd1,
                       const float* __restrict__ Wd2, const float* __restrict__ bd2,
                       float* __restrict__ out)
{
    __shared__ float hs[HID];
    __shared__ float red[4];
    const int b = blockIdx.x;
    const int j = threadIdx.x;

    hs[j]       = hlast[b * HID + j];
    hs[j + 128] = hlast[b * HID + j + 128];
    __syncthreads();

    float acc = bd1[j];
#pragma unroll 8
    for (int k = 0; k < HID; k++) acc = fmaf(hs[k], Wd1[k * 128 + j], acc);
    float hm = fmaxf(acc, 0.f) * Wd2[j];

#pragma unroll
    for (int off = 16; off > 0; off >>= 1)
        hm += __shfl_down_sync(0xffffffffu, hm, off);
    if ((j & 31) == 0) red[j >> 5] = hm;
    __syncthreads();
    if (j == 0) {
        float s = red[0] + red[1] + red[2] + red[3] + bd2[0];
        out[b] = fmaxf(s, 0.f);
    }
}

// ---------------------------------------------------------------------------
extern "C" void kernel_launch(void* const* d_in, const int* in_sizes, int n_in,
                              void* d_out, int out_size)
{
    const float* x   = (const float*)d_in[0];
    const float* W1  = (const float*)d_in[1];
    const float* U1  = (const float*)d_in[2];
    const float* b1  = (const float*)d_in[3];
    const float* W2  = (const float*)d_in[4];
    const float* U2  = (const float*)d_in[5];
    const float* b2  = (const float*)d_in[6];
    const float* Wd1 = (const float*)d_in[7];
    const float* bd1 = (const float*)d_in[8];
    const float* Wd2 = (const float*)d_in[9];
    const float* bd2 = (const float*)d_in[10];
    float* out = (float*)d_out;

    float *xw, *hseq, *hlast;
    cudaGetSymbolAddress((void**)&xw, g_xw);
    cudaGetSymbolAddress((void**)&hseq, g_hseq);
    cudaGetSymbolAddress((void**)&hlast, g_hlast);

    dim3 ggrid(G4 / 128, (BATCH * TLEN) / 128);

    gemm_tf32_bias<<<ggrid, 256>>>(x, W1, b1, xw, 128);
    lstm_layer<true><<<128, 256>>>(xw, U1, hseq, nullptr);
    gemm_tf32_bias<<<ggrid, 256>>>(hseq, W2, b2, xw, 256);
    lstm_layer<false><<<128, 256>>>(xw, U2, nullptr, hlast);
    dense_head_kernel<<<BATCH, 128>>>(hlast, Wd1, bd1, Wd2, bd2, out);
}

// round 16
// speedup vs baseline: 1.2162x; 1.2162x over previous
#include <cuda_runtime.h>
#include <cuda_bf16.h>
#include <cooperative_groups.h>
#include <cstdint>
#include <cstddef>

namespace cg = cooperative_groups;
using u64 = unsigned long long;

#define BATCH 128
#define TLEN  1024
#define HID   256
#define G4    1024  // 4*HID
#define HPAD  260   // hbuf row stride (pad 4 -> conflict-free b-frag LDS)

// ---------------- misc helpers ----------------
__device__ __forceinline__ float sigm_f(float x) {
    x = fminf(fmaxf(x, -30.f), 30.f);
    return __fdividef(1.f, 1.f + __expf(-x));
}
__device__ __forceinline__ float tanh_f(float x) {
    x = fminf(fmaxf(x, -15.f), 15.f);
    float e = __expf(2.f * x);
    return __fdividef(e - 1.f, e + 1.f);
}

// ---------------- tf32 mma helpers ----------------
__device__ __forceinline__ unsigned cvt_tf32(float f) {
    unsigned r;
    asm("cvt.rna.tf32.f32 %0, %1;" : "=r"(r) : "f"(f));
    return r;
}
__device__ __forceinline__ void mma_tf32(float* d, const unsigned* a, const unsigned* b) {
    asm("mma.sync.aligned.m16n8k8.row.col.f32.tf32.tf32.f32 "
        "{%0,%1,%2,%3},{%4,%5,%6,%7},{%8,%9},{%0,%1,%2,%3};"
        : "+f"(d[0]), "+f"(d[1]), "+f"(d[2]), "+f"(d[3])
        : "r"(a[0]), "r"(a[1]), "r"(a[2]), "r"(a[3]), "r"(b[0]), "r"(b[1]));
}

// ---------------- cluster async-store primitives ----------------
__device__ __forceinline__ unsigned smem_u32(const void* p) {
    return (unsigned)__cvta_generic_to_shared(p);
}
__device__ __forceinline__ unsigned mapa_u32(unsigned laddr, unsigned rank) {
    unsigned r;
    asm("mapa.shared::cluster.u32 %0, %1, %2;" : "=r"(r) : "r"(laddr), "r"(rank));
    return r;
}
__device__ __forceinline__ void st_async_u32(unsigned raddr, unsigned v, unsigned rmbar) {
    asm volatile("st.async.shared::cluster.mbarrier::complete_tx::bytes.b32 [%0], %1, [%2];"
                 :: "r"(raddr), "r"(v), "r"(rmbar) : "memory");
}
__device__ __forceinline__ void mbar_init(unsigned mbar, unsigned cnt) {
    asm volatile("mbarrier.init.shared.b64 [%0], %1;" :: "r"(mbar), "r"(cnt) : "memory");
}
__device__ __forceinline__ void mbar_expect_tx(unsigned mbar, unsigned bytes) {
    asm volatile("mbarrier.arrive.expect_tx.shared.b64 _, [%0], %1;"
                 :: "r"(mbar), "r"(bytes) : "memory");
}
__device__ __forceinline__ void mbar_wait_cluster(unsigned mbar, unsigned parity) {
    asm volatile(
        "{\n\t"
        ".reg .pred P;\n"
        "LWAIT_%=:\n\t"
        "mbarrier.try_wait.parity.acquire.cluster.shared::cta.b64 P, [%0], %1, 0x989680;\n\t"
        "@P bra LDONE_%=;\n\t"
        "bra LWAIT_%=;\n"
        "LDONE_%=:\n\t"
        "}"
        :: "r"(mbar), "r"(parity) : "memory");
}

// ---------------- scratch (static device globals) ----------------
__device__ float g_xw[(size_t)BATCH * TLEN * G4];     // 512 MB, reused by both layers
__device__ float g_hseq[(size_t)BATCH * TLEN * HID];  // 128 MB
__device__ float g_hlast[BATCH * HID];

// ---------------------------------------------------------------------------
// tf32 GEMM (R12 version): C[M,1024] = A[M,K] @ B[K,1024] + bias
// 128x128 CTA tile, BK=32, 8 warps (2m x 4n), warp tile 64x32, m16n8k8.
// ---------------------------------------------------------------------------
__global__ __launch_bounds__(256, 2)
void gemm_tf32_bias(const float* __restrict__ A, const float* __restrict__ B,
                    const float* __restrict__ bias, float* __restrict__ C, int K)
{
    __shared__ unsigned As[128][36];
    __shared__ unsigned Bs[32][136];

    const int tid = threadIdx.x;
    const int n0  = blockIdx.x * 128;
    const size_t m0 = (size_t)blockIdx.y * 128;
    const int warp = tid >> 5, lane = tid & 31;
    const int wm = (warp >> 2) * 64;
    const int wn = (warp & 3) * 32;
    const int g  = lane >> 2;
    const int tg = lane & 3;

    float acc[4][4][4];
#pragma unroll
    for (int mf = 0; mf < 4; mf++)
#pragma unroll
        for (int nf = 0; nf < 4; nf++)
#pragma unroll
            for (int i = 0; i < 4; i++) acc[mf][nf][i] = 0.f;

    for (int kb = 0; kb < K; kb += 32) {
#pragma unroll
        for (int i = 0; i < 4; i++) {
            int idx = tid + i * 256;
            int r = idx >> 3, c4 = (idx & 7) * 4;
            float4 v = *(const float4*)&A[(m0 + r) * K + kb + c4];
            uint4 t;
            t.x = cvt_tf32(v.x); t.y = cvt_tf32(v.y);
            t.z = cvt_tf32(v.z); t.w = cvt_tf32(v.w);
            *(uint4*)&As[r][c4] = t;
        }
#pragma unroll
        for (int i = 0; i < 4; i++) {
            int idx = tid + i * 256;
            int r = idx >> 5, c4 = (idx & 31) * 4;
            float4 v = *(const float4*)&B[(size_t)(kb + r) * G4 + n0 + c4];
            uint4 t;
            t.x = cvt_tf32(v.x); t.y = cvt_tf32(v.y);
            t.z = cvt_tf32(v.z); t.w = cvt_tf32(v.w);
            *(uint4*)&Bs[r][c4] = t;
        }
        __syncthreads();

#pragma unroll
        for (int ks = 0; ks < 4; ks++) {
            const int k0 = ks * 8;
            unsigned af[4][4], bf[4][2];
#pragma unroll
            for (int mf = 0; mf < 4; mf++) {
                int row = wm + mf * 16;
                af[mf][0] = As[row + g][k0 + tg];
                af[mf][1] = As[row + g + 8][k0 + tg];
                af[mf][2] = As[row + g][k0 + tg + 4];
                af[mf][3] = As[row + g + 8][k0 + tg + 4];
            }
#pragma unroll
            for (int nf = 0; nf < 4; nf++) {
                int col = wn + nf * 8;
                bf[nf][0] = Bs[k0 + tg][col + g];
                bf[nf][1] = Bs[k0 + tg + 4][col + g];
            }
#pragma unroll
            for (int mf = 0; mf < 4; mf++)
#pragma unroll
                for (int nf = 0; nf < 4; nf++)
                    mma_tf32(acc[mf][nf], af[mf], bf[nf]);
        }
        __syncthreads();
    }

#pragma unroll
    for (int nf = 0; nf < 4; nf++) {
        int col = n0 + wn + nf * 8 + 2 * tg;
        float b0 = bias[col], b1 = bias[col + 1];
#pragma unroll
        for (int mf = 0; mf < 4; mf++) {
            size_t row = m0 + wm + mf * 16 + g;
            float2 v0 = {acc[mf][nf][0] + b0, acc[mf][nf][1] + b1};
            float2 v1 = {acc[mf][nf][2] + b0, acc[mf][nf][3] + b1};
            *(float2*)&C[row * G4 + col] = v0;
            *(float2*)&C[(row + 8) * G4 + col] = v1;
        }
    }
}

// ---------------------------------------------------------------------------
// Persistent-cluster LSTM recurrence — SINGLE-PHASE tensor-core step.
// Grid: 128 CTAs = 16 clusters x 8 CTAs, 256 threads = 8 warps.
// Per step: ONE mbarrier wait (all 8 rows), ONE phase-1 where each warp
// computes D[16 x 8] = U^T[16 x 256] @ h^T[256 x 8] with all 8 batch rows as
// REAL n-columns (32 mma, no padding waste), ONE __syncthreads, ONE epilogue
// in which every warp owns its batch row. st.async exchange as before
// (tf32 bit patterns); mbars[buf] expect 8192 B (8 rows x 32 cols x 8 ranks).
// ---------------------------------------------------------------------------
template <bool WRITE_SEQ>
__global__ void __cluster_dims__(8, 1, 1) __launch_bounds__(256, 1)
lstm_layer(const float* __restrict__ xw, const float* __restrict__ U,
           float* __restrict__ out_seq, float* __restrict__ out_last)
{
    __shared__ __align__(16) unsigned hbuf[2][8][HPAD]; // tf32 bits, dbl-buffered
    __shared__ float part[8][128];                      // [row][gc]
    __shared__ __align__(8) u64 mbars[2];               // [buf]

    cg::cluster_group cluster = cg::this_cluster();
    const int tid  = threadIdx.x;
    const int rank = (int)cluster.block_rank();
    const int cid  = blockIdx.x >> 3;
    const int b0   = cid * 8;

    const int warp = tid >> 5, lane = tid & 31;
    const int g  = lane >> 2;          // 0..7: mma row-group AND B batch-row
    const int tg = lane & 3;           // 0..3

    // epilogue roles: warp er owns batch row er
    const int er = warp;               // 0..7
    const int ec = lane;               // 0..31

    // global column for this warp's m-index
    const int colbase = (warp >> 1) * 256 + rank * 32 + (warp & 1) * 16;

    // U^T fragments: 32 k-chunks x 4 regs (tf32)
    unsigned ua[32][4];
#pragma unroll
    for (int kc = 0; kc < 32; kc++) {
        const int k0 = kc * 8;
        ua[kc][0] = cvt_tf32(U[(size_t)(k0 + tg) * G4 + colbase + g]);
        ua[kc][1] = cvt_tf32(U[(size_t)(k0 + tg) * G4 + colbase + 8 + g]);
        ua[kc][2] = cvt_tf32(U[(size_t)(k0 + tg + 4) * G4 + colbase + g]);
        ua[kc][3] = cvt_tf32(U[(size_t)(k0 + tg + 4) * G4 + colbase + 8 + g]);
    }

    // init smem
    for (int i = tid; i < 2 * 8 * HPAD; i += 256) ((unsigned*)hbuf)[i] = 0u;
    const unsigned mbar0 = smem_u32(&mbars[0]);
    if (tid == 0) { mbar_init(mbar0, 1); mbar_init(mbar0 + 8, 1); }

    // per-rank remote addresses
    const unsigned hloc = smem_u32(&hbuf[0][er][rank * 32 + ec]);
    unsigned rH[8], rM[8];
#pragma unroll
    for (int pr = 0; pr < 8; pr++) {
        rH[pr] = mapa_u32(hloc, pr);
        rM[pr] = mapa_u32(mbar0, pr);
    }

    cluster.sync();   // barriers + zeroed hbuf visible cluster-wide
    if (tid == 0) {
        mbar_expect_tx(mbar0 + 8, 8192);   // buf1: end-of-step-0 writes
        mbar_expect_tx(mbar0, 8192);       // buf0: end-of-step-1 writes
    }

    const float* xptr = xw + ((size_t)(b0 + er) * TLEN) * G4 + rank * 32 + ec;
    float* hptr = WRITE_SEQ
        ? out_seq + ((size_t)(b0 + er) * TLEN) * HID + rank * 32 + ec
        : nullptr;

    float c_state = 0.f;
    unsigned pp0 = 0, pp1 = 0;

    for (int t = 0; t < TLEN; t++) {
        const int p  = t & 1;
        const int nb = p ^ 1;
        const unsigned hoff = (unsigned)(nb * 8 * HPAD) * 4u;
        const unsigned moff = (unsigned)nb * 8u;

        // prefetch own row's xw gate inputs (hide LDG under the wait)
        float xg0 = xptr[0];
        float xg1 = xptr[HID];
        float xg2 = xptr[2 * HID];
        float xg3 = xptr[3 * HID];
        xptr += G4;

        // ---- single wait: all 8 rows' h from all ranks ----
        if (t > 0) {
            if (p == 0) { mbar_wait_cluster(mbar0, pp0); pp0 ^= 1; }
            else        { mbar_wait_cluster(mbar0 + 8, pp1); pp1 ^= 1; }
            if (tid == 0) mbar_expect_tx(mbar0 + (unsigned)p * 8, 8192); // re-arm
        }

        // ---- phase 1: D[16x8] = U^T @ h^T via 32 mma, all rows real ----
        float d0[4] = {0.f, 0.f, 0.f, 0.f};
        float d1[4] = {0.f, 0.f, 0.f, 0.f};
        const unsigned* hrow = &hbuf[p][g][0];   // lane's batch row = g
#pragma unroll
        for (int kc = 0; kc < 32; kc += 2) {
            unsigned b0f[2], b1f[2];
            b0f[0] = hrow[kc * 8 + tg];
            b0f[1] = hrow[kc * 8 + tg + 4];
            b1f[0] = hrow[kc * 8 + 8 + tg];
            b1f[1] = hrow[kc * 8 + 8 + tg + 4];
            mma_tf32(d0, ua[kc], b0f);
            mma_tf32(d1, ua[kc + 1], b1f);
        }
        // D[m][n]: m = warp's 16 cols (g / g+8), n = batch row (2tg, 2tg+1)
        part[2 * tg][warp * 16 + g]         = d0[0] + d1[0];
        part[2 * tg + 1][warp * 16 + g]     = d0[1] + d1[1];
        part[2 * tg][warp * 16 + 8 + g]     = d0[2] + d1[2];
        part[2 * tg + 1][warp * 16 + 8 + g] = d0[3] + d1[3];
        __syncthreads();

        // ---- epilogue: every warp owns its batch row ----
        {
            float v0 = xg0 + part[er][ec];
            float v1 = xg1 + part[er][32 + ec];
            float v2 = xg2 + part[er][64 + ec];
            float v3 = xg3 + part[er][96 + ec];
            float ig = sigm_f(v0);
            float fg = sigm_f(v1);
            float gg = tanh_f(v2);
            float og = sigm_f(v3);
            c_state = fg * c_state + ig * gg;
            float hnew = og * tanh_f(c_state);

            if (WRITE_SEQ) { *hptr = hnew; hptr += HID; }

            if (t < TLEN - 1) {
                const unsigned hb = cvt_tf32(hnew);
#pragma unroll
                for (int pr = 0; pr < 8; pr++)
                    st_async_u32(rH[pr] + hoff, hb, rM[pr] + moff);
            } else if (!WRITE_SEQ) {
                out_last[(size_t)(b0 + er) * HID + rank * 32 + ec] = hnew;
            }
        }
        __syncthreads();   // part[] safe to overwrite next step
    }

    cluster.sync();   // don't exit with peer-targeted async traffic in flight
}

// ---------------------------------------------------------------------------
// Dense head: out[b] = relu( relu(h_last[b] @ Wd1 + bd1) @ Wd2 + bd2 )
// ---------------------------------------------------------------------------
__global__ __launch_bounds__(128)
void dense_head_kernel(const float* __restrict__ hlast,
                       const float* __restrict__ Wd1, const float* __restrict__ bd1,
                       const float* __restrict__ Wd2, const float* __restrict__ bd2,
                       float* __restrict__ out)
{
    __shared__ float hs[HID];
    __shared__ float red[4];
    const int b = blockIdx.x;
    const int j = threadIdx.x;

    hs[j]       = hlast[b * HID + j];
    hs[j + 128] = hlast[b * HID + j + 128];
    __syncthreads();

    float acc = bd1[j];
#pragma unroll 8
    for (int k = 0; k < HID; k++) acc = fmaf(hs[k], Wd1[k * 128 + j], acc);
    float hm = fmaxf(acc, 0.f) * Wd2[j];

#pragma unroll
    for (int off = 16; off > 0; off >>= 1)
        hm += __shfl_down_sync(0xffffffffu, hm, off);
    if ((j & 31) == 0) red[j >> 5] = hm;
    __syncthreads();
    if (j == 0) {
        float s = red[0] + red[1] + red[2] + red[3] + bd2[0];
        out[b] = fmaxf(s, 0.f);
    }
}

// ---------------------------------------------------------------------------
extern "C" void kernel_launch(void* const* d_in, const int* in_sizes, int n_in,
                              void* d_out, int out_size)
{
    const float* x   = (const float*)d_in[0];
    const float* W1  = (const float*)d_in[1];
    const float* U1  = (const float*)d_in[2];
    const float* b1  = (const float*)d_in[3];
    const float* W2  = (const float*)d_in[4];
    const float* U2  = (const float*)d_in[5];
    const float* b2  = (const float*)d_in[6];
    const float* Wd1 = (const float*)d_in[7];
    const float* bd1 = (const float*)d_in[8];
    const float* Wd2 = (const float*)d_in[9];
    const float* bd2 = (const float*)d_in[10];
    float* out = (float*)d_out;

    float *xw, *hseq, *hlast;
    cudaGetSymbolAddress((void**)&xw, g_xw);
    cudaGetSymbolAddress((void**)&hseq, g_hseq);
    cudaGetSymbolAddress((void**)&hlast, g_hlast);

    dim3 ggrid(G4 / 128, (BATCH * TLEN) / 128);

    gemm_tf32_bias<<<ggrid, 256>>>(x, W1, b1, xw, 128);
    lstm_layer<true><<<128, 256>>>(xw, U1, hseq, nullptr);
    gemm_tf32_bias<<<ggrid, 256>>>(hseq, W2, b2, xw, 256);
    lstm_layer<false><<<128, 256>>>(xw, U2, nullptr, hlast);
    dense_head_kernel<<<BATCH, 128>>>(hlast, Wd1, bd1, Wd2, bd2, out);
}